// round 11
// baseline (speedup 1.0000x reference)
#include <cuda_runtime.h>
#include <cuda_bf16.h>
#include <cstdint>
#include <math.h>

#define B_    8192
#define T_    30
#define D_    256
#define H_    8
#define L_    6
#define SD_   8
#define FF_   1024
#define CF_   256
#define BT_   (B_*T_)
#define KP_   320   // 296 padded to multiple of 64
#define NAD_  6144  // 12 * 512 batched adaLN output width

// ============================ ptx helpers ============================
#define SWZ(x) ((x) ^ (((x) >> 3) & 0x70))

static __device__ __forceinline__ uint32_t s2u(const void* p){
    uint32_t a;
    asm("{ .reg .u64 t; cvta.to.shared.u64 t, %1; cvt.u32.u64 %0, t; }" : "=r"(a) : "l"(p));
    return a;
}
static __device__ __forceinline__ void cpa16(uint32_t s, const void* g){
    asm volatile("cp.async.cg.shared.global [%0], [%1], 16;" :: "r"(s), "l"(g));
}
#define CP_COMMIT() asm volatile("cp.async.commit_group;" ::: "memory")
#define CP_WAIT1()  asm volatile("cp.async.wait_group 1;" ::: "memory")
#define CP_WAIT0()  asm volatile("cp.async.wait_group 0;" ::: "memory")

static __device__ __forceinline__ void ldm4(uint32_t a, uint32_t* r){
    asm volatile("ldmatrix.sync.aligned.m8n8.x4.shared.b16 {%0,%1,%2,%3}, [%4];"
        : "=r"(r[0]), "=r"(r[1]), "=r"(r[2]), "=r"(r[3]) : "r"(a));
}
static __device__ __forceinline__ void mma16816(float* d,
    uint32_t a0, uint32_t a1, uint32_t a2, uint32_t a3, uint32_t b0, uint32_t b1){
    asm volatile(
        "mma.sync.aligned.m16n8k16.row.col.f32.bf16.bf16.f32 "
        "{%0,%1,%2,%3}, {%4,%5,%6,%7}, {%8,%9}, {%0,%1,%2,%3};"
        : "+f"(d[0]), "+f"(d[1]), "+f"(d[2]), "+f"(d[3])
        : "r"(a0), "r"(a1), "r"(a2), "r"(a3), "r"(b0), "r"(b1));
}

// ============================ scratch ============================
__device__ float g_ss [(size_t)B_*NAD_];   // batched adaLN outputs
__device__ float g_adb[NAD_];              // concatenated adaLN biases
__device__ float g_u  [B_*SD_];
__device__ float g_part[1024];
__device__ __align__(256) __nv_bfloat16 g_xb [(size_t)BT_*D_];   // residual stream (bf16)
__device__ __align__(256) __nv_bfloat16 g_x2b[(size_t)BT_*D_];
__device__ __align__(256) __nv_bfloat16 g_hb [(size_t)BT_*FF_];
__device__ __align__(256) __nv_bfloat16 g_cb [B_*CF_];
__device__ __align__(256) __nv_bfloat16 g_canvb[B_*384];
__device__ __align__(256) __nv_bfloat16 g_f1b[B_*512];
__device__ __align__(256) __nv_bfloat16 g_f2b[B_*512];
__device__ __align__(256) __nv_bfloat16 g_xinb[B_*KP_];
__device__ __align__(256) __nv_bfloat16 g_wce1[512*384];
__device__ __align__(256) __nv_bfloat16 g_wce2[256*512];
__device__ __align__(256) __nv_bfloat16 g_wad [NAD_*256];        // [adaln1(L*512); adaln2(L*512)] x 256
__device__ __align__(256) __nv_bfloat16 g_winp[L_*768*256];
__device__ __align__(256) __nv_bfloat16 g_wout[L_*256*256];
__device__ __align__(256) __nv_bfloat16 g_wff1[(size_t)L_*1024*256];
__device__ __align__(256) __nv_bfloat16 g_wff2[(size_t)L_*256*1024];
__device__ __align__(256) __nv_bfloat16 g_wfm1[512*KP_];
__device__ __align__(256) __nv_bfloat16 g_wfm2[512*512];

// ============================ streaming bf16 HMMA GEMM ============================
// (used for K != 256 shapes: canvas, ff2, flow head)
#define GSMEM (3*32768 + 1024)

static __device__ __forceinline__ void load_stage(
    uint32_t ab, int s, const __nv_bfloat16* A, const __nv_bfloat16* W,
    int K, int bm, int bn, int k0, int tid)
{
    uint32_t as_ = ab + s*32768;
    uint32_t bs_ = as_ + 16384;
    const __nv_bfloat16* Ap = A + (size_t)bm*K + k0;
    const __nv_bfloat16* Wp = W + (size_t)bn*K + k0;
#pragma unroll
    for (int t = 0; t < 4; t++) {
        int idx = tid + t*256;
        int row = idx >> 3, c16 = idx & 7;
        uint32_t off = (uint32_t)(row*128 + c16*16);
        cpa16(as_ + SWZ(off), Ap + (size_t)row*K + c16*8);
    }
#pragma unroll
    for (int t = 0; t < 4; t++) {
        int idx = tid + t*256;
        int row = idx >> 3, c16 = idx & 7;
        uint32_t off = (uint32_t)(row*128 + c16*16);
        cpa16(bs_ + SWZ(off), Wp + (size_t)row*K + c16*8);
    }
}

template<int EPI, int OUTBF>
__global__ __launch_bounds__(256, 2)
void gemm_tc(const __nv_bfloat16* __restrict__ A, const __nv_bfloat16* __restrict__ W,
             const float* __restrict__ bias, void* __restrict__ Cout,
             const void* __restrict__ res, int M, int N, int K)
{
    extern __shared__ char smem[];
    const int tid = threadIdx.x;
    uint32_t sraw = s2u(smem);
    uint32_t ab = (sraw + 1023) & ~1023u;
    char* smemc = smem + (ab - sraw);
    const int bm = blockIdx.y * 128;
    const int bn = blockIdx.x * 128;
    const int lane = tid & 31, wid = tid >> 5;
    const int wm = (wid & 3) * 32;
    const int wn = (wid >> 2) * 64;

    float acc[2][8][4];
#pragma unroll
    for (int a = 0; a < 2; a++)
#pragma unroll
        for (int b = 0; b < 8; b++)
#pragma unroll
            for (int c = 0; c < 4; c++) acc[a][b][c] = 0.f;

    const int nch = K >> 6;
    load_stage(ab, 0, A, W, K, bm, bn, 0,  tid); CP_COMMIT();
    load_stage(ab, 1, A, W, K, bm, bn, 64, tid); CP_COMMIT();

    const int r16 = lane & 15;
    const uint32_t cg = (uint32_t)((lane >> 4) << 4);

    int s = 0;
    for (int i = 0; i < nch; i++) {
        CP_WAIT1();
        __syncthreads();
        if (i + 2 < nch) {
            int s2 = s + 2; if (s2 >= 3) s2 -= 3;
            load_stage(ab, s2, A, W, K, bm, bn, (i+2)*64, tid);
        }
        CP_COMMIT();

        const uint32_t as_ = ab + s*32768;
        const uint32_t bs_ = as_ + 16384;
#pragma unroll
        for (int k16 = 0; k16 < 4; k16++) {
            uint32_t af[2][4], bfr[4][4];
#pragma unroll
            for (int mt = 0; mt < 2; mt++) {
                uint32_t off = (uint32_t)((wm + mt*16 + r16)*128 + k16*32) + cg;
                ldm4(as_ + SWZ(off), af[mt]);
            }
#pragma unroll
            for (int nt2 = 0; nt2 < 4; nt2++) {
                uint32_t off = (uint32_t)((wn + nt2*16 + r16)*128 + k16*32) + cg;
                ldm4(bs_ + SWZ(off), bfr[nt2]);
            }
#pragma unroll
            for (int mt = 0; mt < 2; mt++)
#pragma unroll
                for (int nt2 = 0; nt2 < 4; nt2++) {
                    mma16816(acc[mt][nt2*2],   af[mt][0], af[mt][1], af[mt][2], af[mt][3],
                             bfr[nt2][0], bfr[nt2][2]);
                    mma16816(acc[mt][nt2*2+1], af[mt][0], af[mt][1], af[mt][2], af[mt][3],
                             bfr[nt2][1], bfr[nt2][3]);
                }
        }
        if (++s >= 3) s = 0;
    }
    CP_WAIT0();
    __syncthreads();

    float* smemT = (float*)smemc;
    {
        const int r4 = lane >> 2;
        const int c2 = (lane & 3) << 1;
#pragma unroll
        for (int mt = 0; mt < 2; mt++)
#pragma unroll
            for (int nt = 0; nt < 8; nt++) {
                int row = wm + mt*16 + r4;
                int col = wn + nt*8 + c2;
                *(float2*)&smemT[row*132 + col]     = make_float2(acc[mt][nt][0], acc[mt][nt][1]);
                *(float2*)&smemT[(row+8)*132 + col] = make_float2(acc[mt][nt][2], acc[mt][nt][3]);
            }
    }
    __syncthreads();
#pragma unroll
    for (int it = 0; it < 16; it++) {
        int idx = tid + it*256;
        int row = idx >> 5;
        int c4  = (idx & 31) << 2;
        float4 v = *(float4*)&smemT[row*132 + c4];
        float4 bb = *(const float4*)&bias[bn + c4];
        v.x += bb.x; v.y += bb.y; v.z += bb.z; v.w += bb.w;
        if (EPI == 1) {
            v.x *= 1.f/(1.f + __expf(-v.x));
            v.y *= 1.f/(1.f + __expf(-v.y));
            v.z *= 1.f/(1.f + __expf(-v.z));
            v.w *= 1.f/(1.f + __expf(-v.w));
        }
        size_t g = (size_t)(bm + row)*N + bn + c4;
        if (EPI == 2) {
            uint2 rr = *(const uint2*)((const __nv_bfloat16*)res + g);
            __nv_bfloat162 r0 = *(__nv_bfloat162*)&rr.x;
            __nv_bfloat162 r1 = *(__nv_bfloat162*)&rr.y;
            v.x += __bfloat162float(r0.x); v.y += __bfloat162float(r0.y);
            v.z += __bfloat162float(r1.x); v.w += __bfloat162float(r1.y);
        }
        if (OUTBF) {
            __nv_bfloat162 p0 = __floats2bfloat162_rn(v.x, v.y);
            __nv_bfloat162 p1 = __floats2bfloat162_rn(v.z, v.w);
            uint2 u2;
            u2.x = *(uint32_t*)&p0; u2.y = *(uint32_t*)&p1;
            *(uint2*)((__nv_bfloat16*)Cout + g) = u2;
        } else {
            *(float4*)((float*)Cout + g) = v;
        }
    }
}

// ============================ persistent W-resident GEMM (K=256) ============================
// Each CTA pins W[bn:bn+128, 0:256] in smem (64KB, 4 swizzled k-chunks) and streams
// A-tiles through a 3-stage pipeline that runs continuously across its M-tiles.
// Direct register->global epilogue (no smem, no barriers). grid.x = nbn * G.
#define GSMEM2 (65536 + 3*16384 + 1024)   // 115712 -> 2 CTAs/SM (226KB/SM)

template<int EPI, int OUTBF>
__global__ __launch_bounds__(256, 2)
void gemm_pw(const __nv_bfloat16* __restrict__ A, const __nv_bfloat16* __restrict__ W,
             const float* __restrict__ bias, void* __restrict__ Cout,
             const void* __restrict__ res, int M, int N, int nbn)
{
    extern __shared__ char smem[];
    const int tid = threadIdx.x;
    uint32_t sraw = s2u(smem);
    uint32_t ab = (sraw + 1023) & ~1023u;
    const int G  = gridDim.x / nbn;
    const int g0 = blockIdx.x / nbn;
    const int bn = (blockIdx.x % nbn) * 128;
    const int nmt = M >> 7;
    const int lane = tid & 31, wid = tid >> 5;
    const int wm = (wid & 3) * 32;
    const int wn = (wid >> 2) * 64;
    const uint32_t Wb = ab;
    const uint32_t Ab = ab + 65536;

    // pin W: 128 rows x 256 k as 4 swizzled 16KB k-chunks
#pragma unroll
    for (int c = 0; c < 4; c++)
#pragma unroll
        for (int t = 0; t < 4; t++) {
            int idx = tid + t*256;
            int row = idx >> 3, c16 = idx & 7;
            uint32_t off = (uint32_t)(row*128 + c16*16);
            cpa16(Wb + c*16384 + SWZ(off), W + (size_t)(bn+row)*256 + c*64 + c16*8);
        }
    CP_COMMIT();

    int tiles = 0;
    for (int m = g0; m < nmt; m += G) tiles++;
    if (tiles == 0) { CP_WAIT0(); return; }
    const int totq = tiles * 4;

    auto issueA = [&](int q){
        int bm = (g0 + (q >> 2)*G) << 7;
        int k0 = (q & 3) << 6;
        uint32_t as_ = Ab + (q % 3)*16384;
        const __nv_bfloat16* Ap = A + (size_t)bm*256 + k0;
#pragma unroll
        for (int t = 0; t < 4; t++) {
            int idx = tid + t*256;
            int row = idx >> 3, c16 = idx & 7;
            uint32_t off = (uint32_t)(row*128 + c16*16);
            cpa16(as_ + SWZ(off), Ap + (size_t)row*256 + c16*8);
        }
    };
    issueA(0); CP_COMMIT();
    if (totq > 1) issueA(1);
    CP_COMMIT();

    float acc[2][8][4];
#pragma unroll
    for (int a = 0; a < 2; a++)
#pragma unroll
        for (int b = 0; b < 8; b++)
#pragma unroll
            for (int c = 0; c < 4; c++) acc[a][b][c] = 0.f;

    const int r16 = lane & 15;
    const uint32_t cg = (uint32_t)((lane >> 4) << 4);

    for (int q = 0; q < totq; q++) {
        CP_WAIT1();
        __syncthreads();          // all warps done with chunk q-1 before reusing its stage
        if (q + 2 < totq) issueA(q + 2);
        CP_COMMIT();

        const uint32_t as_ = Ab + (q % 3)*16384;
        const uint32_t bs_ = Wb + (q & 3)*16384;
#pragma unroll
        for (int k16 = 0; k16 < 4; k16++) {
            uint32_t af[2][4], bfr[4][4];
#pragma unroll
            for (int mt = 0; mt < 2; mt++) {
                uint32_t off = (uint32_t)((wm + mt*16 + r16)*128 + k16*32) + cg;
                ldm4(as_ + SWZ(off), af[mt]);
            }
#pragma unroll
            for (int nt2 = 0; nt2 < 4; nt2++) {
                uint32_t off = (uint32_t)((wn + nt2*16 + r16)*128 + k16*32) + cg;
                ldm4(bs_ + SWZ(off), bfr[nt2]);
            }
#pragma unroll
            for (int mt = 0; mt < 2; mt++)
#pragma unroll
                for (int nt2 = 0; nt2 < 4; nt2++) {
                    mma16816(acc[mt][nt2*2],   af[mt][0], af[mt][1], af[mt][2], af[mt][3],
                             bfr[nt2][0], bfr[nt2][2]);
                    mma16816(acc[mt][nt2*2+1], af[mt][0], af[mt][1], af[mt][2], af[mt][3],
                             bfr[nt2][1], bfr[nt2][3]);
                }
        }

        if ((q & 3) == 3) {
            // direct epilogue for tile q>>2 (registers -> global, sector-aligned)
            int bm = (g0 + (q >> 2)*G) << 7;
            const int r4 = lane >> 2;
            const int c2 = (lane & 3) << 1;
#pragma unroll
            for (int mt = 0; mt < 2; mt++)
#pragma unroll
                for (int nt = 0; nt < 8; nt++) {
                    int col = bn + wn + nt*8 + c2;
                    float b0 = __ldg(&bias[col]);
                    float b1 = __ldg(&bias[col+1]);
#pragma unroll
                    for (int hr = 0; hr < 2; hr++) {
                        int row = bm + wm + mt*16 + r4 + hr*8;
                        float v0 = acc[mt][nt][hr*2+0] + b0;
                        float v1 = acc[mt][nt][hr*2+1] + b1;
                        if (EPI == 1) {
                            v0 *= 1.f/(1.f + __expf(-v0));
                            v1 *= 1.f/(1.f + __expf(-v1));
                        }
                        size_t g = (size_t)row*N + col;
                        if (EPI == 2) {
                            uint32_t rr = *(const uint32_t*)((const __nv_bfloat16*)res + g);
                            __nv_bfloat162 r0 = *(__nv_bfloat162*)&rr;
                            v0 += __bfloat162float(r0.x);
                            v1 += __bfloat162float(r0.y);
                        }
                        if (OUTBF) {
                            __nv_bfloat162 p = __floats2bfloat162_rn(v0, v1);
                            *(uint32_t*)((__nv_bfloat16*)Cout + g) = *(uint32_t*)&p;
                        } else {
                            *(float2*)((float*)Cout + g) = make_float2(v0, v1);
                        }
                        acc[mt][nt][hr*2+0] = 0.f;
                        acc[mt][nt][hr*2+1] = 0.f;
                    }
                }
        }
    }
    CP_WAIT0();
}

// ============================ aux kernels ============================
__global__ void k_cvt(const float* __restrict__ s, __nv_bfloat16* __restrict__ d, int n)
{
    for (int i = blockIdx.x*blockDim.x + threadIdx.x; i < n; i += gridDim.x*blockDim.x)
        d[i] = __float2bfloat16(s[i]);
}

__global__ void k_cat(const float* __restrict__ b1, const float* __restrict__ b2,
                      float* __restrict__ d)
{
    int i = blockIdx.x*blockDim.x + threadIdx.x;   // 6144 total
    d[i] = (i < 3072) ? b1[i] : b2[i - 3072];
}

__global__ __launch_bounds__(256)
void k_stroke(const float* __restrict__ strokes, const float* __restrict__ sp_w,
              const float* __restrict__ sp_b, const float* __restrict__ pos,
              __nv_bfloat16* __restrict__ x)
{
    int row = blockIdx.x;
    int t = row % T_;
    int d = threadIdx.x;
    float acc = sp_b[d] + pos[t*D_ + d];
#pragma unroll
    for (int j = 0; j < 8; j++)
        acc += strokes[(size_t)row*8 + j] * sp_w[d*8 + j];
    x[(size_t)row*D_ + d] = __float2bfloat16(acc);
}

static __device__ __forceinline__ void unp8(uint4 u, float* v){
    __nv_bfloat162 p0 = *(__nv_bfloat162*)&u.x;
    __nv_bfloat162 p1 = *(__nv_bfloat162*)&u.y;
    __nv_bfloat162 p2 = *(__nv_bfloat162*)&u.z;
    __nv_bfloat162 p3 = *(__nv_bfloat162*)&u.w;
    v[0] = __bfloat162float(p0.x); v[1] = __bfloat162float(p0.y);
    v[2] = __bfloat162float(p1.x); v[3] = __bfloat162float(p1.y);
    v[4] = __bfloat162float(p2.x); v[5] = __bfloat162float(p2.y);
    v[6] = __bfloat162float(p3.x); v[7] = __bfloat162float(p3.y);
}

// warp-per-row adaLN modulate: x2 = (1+sc)*LN(x) + sh; ss is [B, 6144], slice at off
__global__ __launch_bounds__(256)
void k_modln(const __nv_bfloat16* __restrict__ x, const float* __restrict__ ss,
             __nv_bfloat16* __restrict__ x2, int off)
{
    int w = threadIdx.x >> 5, ln = threadIdx.x & 31;
    int row = blockIdx.x*8 + w;
    int b = row / T_;
    float v[8];
    unp8(*(const uint4*)(x + (size_t)row*D_ + ln*8), v);
    float s = 0.f, q = 0.f;
#pragma unroll
    for (int j = 0; j < 8; j++) { s += v[j]; q += v[j]*v[j]; }
#pragma unroll
    for (int o = 16; o; o >>= 1) {
        s += __shfl_xor_sync(0xffffffffu, s, o);
        q += __shfl_xor_sync(0xffffffffu, q, o);
    }
    float mean = s * (1.f/256.f);
    float rstd = rsqrtf(q * (1.f/256.f) - mean*mean + 1e-5f);
    const float* ssb = ss + (size_t)b*NAD_ + off;
    float sc[8], sh[8];
    *(float4*)&sc[0] = *(const float4*)&ssb[ln*8];
    *(float4*)&sc[4] = *(const float4*)&ssb[ln*8 + 4];
    *(float4*)&sh[0] = *(const float4*)&ssb[256 + ln*8];
    *(float4*)&sh[4] = *(const float4*)&ssb[256 + ln*8 + 4];
    float o8[8];
#pragma unroll
    for (int j = 0; j < 8; j++)
        o8[j] = (1.f + sc[j])*((v[j] - mean)*rstd) + sh[j];
    __nv_bfloat162 p0 = __floats2bfloat162_rn(o8[0], o8[1]);
    __nv_bfloat162 p1 = __floats2bfloat162_rn(o8[2], o8[3]);
    __nv_bfloat162 p2 = __floats2bfloat162_rn(o8[4], o8[5]);
    __nv_bfloat162 p3 = __floats2bfloat162_rn(o8[6], o8[7]);
    uint4 u4;
    u4.x = *(uint32_t*)&p0; u4.y = *(uint32_t*)&p1;
    u4.z = *(uint32_t*)&p2; u4.w = *(uint32_t*)&p3;
    *(uint4*)&x2[(size_t)row*D_ + ln*8] = u4;
}

// ============================ attention ============================
#define ASMEM (2*T_*256*4)   // 61440
__global__ __launch_bounds__(256)
void k_attn(const __nv_bfloat16* __restrict__ qkv, __nv_bfloat16* __restrict__ o)
{
    extern __shared__ float att[];
    float* ks = att;              // [T_][256]
    float* vs = att + T_*256;     // [T_][256]
    int b = blockIdx.x;
    int tid = threadIdx.x;
    int h = tid >> 5, ln = tid & 31;

#pragma unroll
    for (int it = 0; it < T_; it++) {
        int i = tid + it*256;
        int t = i >> 8, d = i & 255;
        size_t base = ((size_t)(b*T_ + t))*768 + d;
        ks[t*256 + d] = __bfloat162float(qkv[base + 256]);
        vs[t*256 + d] = __bfloat162float(qkv[base + 512]);
    }
    __syncthreads();

    if (ln < T_) {
        const int q = ln;
        float qreg[32];
        const __nv_bfloat16* qp = qkv + ((size_t)(b*T_ + q))*768 + h*32;
#pragma unroll
        for (int d4 = 0; d4 < 4; d4++) {
            float v8[8];
            unp8(*(const uint4*)(qp + d4*8), v8);
#pragma unroll
            for (int j = 0; j < 8; j++) qreg[d4*8 + j] = v8[j];
        }
        const float* kh = ks + h*32;
        const float* vh = vs + h*32;
        const float scale = 0.17677669529663687f;

        float sc[T_];
#pragma unroll
        for (int k = 0; k < T_; k++) {
            float acc = 0.f;
#pragma unroll
            for (int d = 0; d < 32; d++) acc += qreg[d]*kh[k*256 + d];
            sc[k] = (k <= q) ? acc*scale : -1e30f;
        }
        float mx = -1e30f;
#pragma unroll
        for (int k = 0; k < T_; k++) mx = fmaxf(mx, sc[k]);
        float sm = 0.f;
#pragma unroll
        for (int k = 0; k < T_; k++) { sc[k] = __expf(sc[k] - mx); sm += sc[k]; }
        float inv = 1.f/sm;

        float o32[32];
#pragma unroll
        for (int d = 0; d < 32; d++) o32[d] = 0.f;
#pragma unroll
        for (int k = 0; k < T_; k++) {
            float a = sc[k]*inv;
            if (k <= q) {
#pragma unroll
                for (int d = 0; d < 32; d++) o32[d] += a*vh[k*256 + d];
            }
        }
        __nv_bfloat16* op = o + ((size_t)(b*T_ + q))*256 + h*32;
#pragma unroll
        for (int d4 = 0; d4 < 4; d4++) {
            __nv_bfloat162 p0 = __floats2bfloat162_rn(o32[d4*8+0], o32[d4*8+1]);
            __nv_bfloat162 p1 = __floats2bfloat162_rn(o32[d4*8+2], o32[d4*8+3]);
            __nv_bfloat162 p2 = __floats2bfloat162_rn(o32[d4*8+4], o32[d4*8+5]);
            __nv_bfloat162 p3 = __floats2bfloat162_rn(o32[d4*8+6], o32[d4*8+7]);
            uint4 u4;
            u4.x = *(uint32_t*)&p0; u4.y = *(uint32_t*)&p1;
            u4.z = *(uint32_t*)&p2; u4.w = *(uint32_t*)&p3;
            *(uint4*)(op + d4*8) = u4;
        }
    }
}

// fused head: final LN on last token + xin tail + u   (8 b per block, warp each)
__global__ __launch_bounds__(256)
void k_head(const __nv_bfloat16* __restrict__ x, const float* __restrict__ g,
            const float* __restrict__ be, const float* __restrict__ a_tar,
            const float* __restrict__ a_src, const float* __restrict__ t,
            __nv_bfloat16* __restrict__ xin, float* __restrict__ u)
{
    int w = threadIdx.x >> 5, ln = threadIdx.x & 31;
    int b = blockIdx.x*8 + w;
    float v[8];
    unp8(*(const uint4*)(x + ((size_t)(b*T_ + T_ - 1))*D_ + ln*8), v);
    float s = 0.f, q = 0.f;
#pragma unroll
    for (int j = 0; j < 8; j++) { s += v[j]; q += v[j]*v[j]; }
#pragma unroll
    for (int o = 16; o; o >>= 1) {
        s += __shfl_xor_sync(0xffffffffu, s, o);
        q += __shfl_xor_sync(0xffffffffu, q, o);
    }
    float mean = s * (1.f/256.f);
    float rstd = rsqrtf(q * (1.f/256.f) - mean*mean + 1e-5f);
    size_t base = (size_t)b*KP_;
#pragma unroll
    for (int j = 0; j < 8; j++) {
        int d = ln*8 + j;
        xin[base + d] = __float2bfloat16(((v[j] - mean)*rstd)*g[d] + be[d]);
    }
    float tb = t[b];
    if (ln < 8) {
        float as = a_src[b*8+ln], at = a_tar[b*8+ln];
        xin[base + 256 + ln] = __float2bfloat16((1.f - tb)*as + tb*at);
        u[b*8+ln] = at - as;
    } else if (ln < 24) {
        int j = ln - 8;
        float freq = __expf(-9.210340371976184f * (float)j / 15.f);
        float arg = tb * freq;
        xin[base + 264 + j] = __float2bfloat16(sinf(arg));
        xin[base + 280 + j] = __float2bfloat16(cosf(arg));
    } else {
        int j0 = (ln - 24) * 3;
#pragma unroll
        for (int k = 0; k < 3; k++)
            xin[base + 296 + j0 + k] = __float2bfloat16(0.f);
    }
}

__global__ void k_padw(const float* __restrict__ w, __nv_bfloat16* __restrict__ wp)
{
    int n = blockIdx.x, k = threadIdx.x;   // 320 threads
    wp[n*KP_ + k] = __float2bfloat16(k < 296 ? w[n*296 + k] : 0.f);
}

__global__ __launch_bounds__(256)
void k_fm3(const __nv_bfloat16* __restrict__ f2, const float* __restrict__ w3,
           const float* __restrict__ b3, const float* __restrict__ u,
           float* __restrict__ part)
{
    __shared__ float sp[8];
    int w = threadIdx.x >> 5, ln = threadIdx.x & 31;
    int b = blockIdx.x * 8 + w;
    float lsum = 0.f;
    const __nv_bfloat16* fr = f2 + (size_t)b*512;
#pragma unroll
    for (int n = 0; n < 8; n++) {
        const float* wr = w3 + n*512;
        float p = 0.f;
        for (int k = ln; k < 512; k += 32) p += __bfloat162float(fr[k])*wr[k];
#pragma unroll
        for (int o = 16; o; o >>= 1) p += __shfl_xor_sync(0xffffffffu, p, o);
        if (ln == 0) {
            float d = p + b3[n] - u[b*8+n];
            lsum += d*d;
        }
    }
    if (ln == 0) sp[w] = lsum;
    __syncthreads();
    if (threadIdx.x == 0) {
        float s = 0.f;
        for (int i = 0; i < 8; i++) s += sp[i];
        part[blockIdx.x] = s;
    }
}

__global__ void k_reduce(const float* __restrict__ part, float* __restrict__ out)
{
    __shared__ float sp[1024];
    int i = threadIdx.x;
    sp[i] = part[i];
    __syncthreads();
    for (int s = 512; s; s >>= 1) { if (i < s) sp[i] += sp[i+s]; __syncthreads(); }
    if (i == 0) out[0] = sp[0] * (1.f / (float)(B_*SD_));
}

// ============================ launch ============================
extern "C" void kernel_launch(void* const* d_in, const int* in_sizes, int n_in,
                              void* d_out, int out_size)
{
    const float* strokes  = (const float*)d_in[0];
    const float* canvas   = (const float*)d_in[1];
    const float* a_tar    = (const float*)d_in[2];
    const float* a_src    = (const float*)d_in[3];
    const float* t_in     = (const float*)d_in[4];
    const float* ce_w1    = (const float*)d_in[5];
    const float* ce_b1    = (const float*)d_in[6];
    const float* ce_w2    = (const float*)d_in[7];
    const float* ce_b2    = (const float*)d_in[8];
    const float* sp_w     = (const float*)d_in[9];
    const float* sp_b     = (const float*)d_in[10];
    const float* pos_emb  = (const float*)d_in[11];
    const float* adaln1_w = (const float*)d_in[12];
    const float* adaln1_b = (const float*)d_in[13];
    const float* inproj_w = (const float*)d_in[14];
    const float* inproj_b = (const float*)d_in[15];
    const float* outproj_w= (const float*)d_in[16];
    const float* outproj_b= (const float*)d_in[17];
    const float* adaln2_w = (const float*)d_in[18];
    const float* adaln2_b = (const float*)d_in[19];
    const float* ff1_w    = (const float*)d_in[20];
    const float* ff1_b    = (const float*)d_in[21];
    const float* ff2_w    = (const float*)d_in[22];
    const float* ff2_b    = (const float*)d_in[23];
    const float* on_g     = (const float*)d_in[24];
    const float* on_b     = (const float*)d_in[25];
    const float* fm_w1    = (const float*)d_in[26];
    const float* fm_b1    = (const float*)d_in[27];
    const float* fm_w2    = (const float*)d_in[28];
    const float* fm_b2    = (const float*)d_in[29];
    const float* fm_w3    = (const float*)d_in[30];
    const float* fm_b3    = (const float*)d_in[31];
    float* out = (float*)d_out;

    float *ss, *adb, *u, *part;
    __nv_bfloat16 *xb, *x2b, *hb, *cb, *canvb, *f1b, *f2b, *xinb;
    __nv_bfloat16 *wce1, *wce2, *wad, *winp, *wout, *wff1, *wff2, *wfm1, *wfm2;
    cudaGetSymbolAddress((void**)&ss,   g_ss);
    cudaGetSymbolAddress((void**)&adb,  g_adb);
    cudaGetSymbolAddress((void**)&u,    g_u);
    cudaGetSymbolAddress((void**)&part, g_part);
    cudaGetSymbolAddress((void**)&xb,   g_xb);
    cudaGetSymbolAddress((void**)&x2b,  g_x2b);
    cudaGetSymbolAddress((void**)&hb,   g_hb);
    cudaGetSymbolAddress((void**)&cb,   g_cb);
    cudaGetSymbolAddress((void**)&canvb,g_canvb);
    cudaGetSymbolAddress((void**)&f1b,  g_f1b);
    cudaGetSymbolAddress((void**)&f2b,  g_f2b);
    cudaGetSymbolAddress((void**)&xinb, g_xinb);
    cudaGetSymbolAddress((void**)&wce1, g_wce1);
    cudaGetSymbolAddress((void**)&wce2, g_wce2);
    cudaGetSymbolAddress((void**)&wad,  g_wad);
    cudaGetSymbolAddress((void**)&winp, g_winp);
    cudaGetSymbolAddress((void**)&wout, g_wout);
    cudaGetSymbolAddress((void**)&wff1, g_wff1);
    cudaGetSymbolAddress((void**)&wff2, g_wff2);
    cudaGetSymbolAddress((void**)&wfm1, g_wfm1);
    cudaGetSymbolAddress((void**)&wfm2, g_wfm2);

    cudaFuncSetAttribute(gemm_tc<0,1>, cudaFuncAttributeMaxDynamicSharedMemorySize, GSMEM);
    cudaFuncSetAttribute(gemm_tc<1,1>, cudaFuncAttributeMaxDynamicSharedMemorySize, GSMEM);
    cudaFuncSetAttribute(gemm_tc<2,1>, cudaFuncAttributeMaxDynamicSharedMemorySize, GSMEM);
    cudaFuncSetAttribute(gemm_pw<0,0>, cudaFuncAttributeMaxDynamicSharedMemorySize, GSMEM2);
    cudaFuncSetAttribute(gemm_pw<0,1>, cudaFuncAttributeMaxDynamicSharedMemorySize, GSMEM2);
    cudaFuncSetAttribute(gemm_pw<1,1>, cudaFuncAttributeMaxDynamicSharedMemorySize, GSMEM2);
    cudaFuncSetAttribute(gemm_pw<2,1>, cudaFuncAttributeMaxDynamicSharedMemorySize, GSMEM2);
    cudaFuncSetAttribute(k_attn,       cudaFuncAttributeMaxDynamicSharedMemorySize, ASMEM);

    // weight + input bf16 conversion
    k_cvt<<<1024, 256>>>(canvas,   canvb, B_*384);
    k_cvt<<<256,  256>>>(ce_w1,    wce1,  512*384);
    k_cvt<<<256,  256>>>(ce_w2,    wce2,  256*512);
    k_cvt<<<512,  256>>>(adaln1_w, wad,             L_*512*256);
    k_cvt<<<512,  256>>>(adaln2_w, wad + 3072*256,  L_*512*256);
    k_cat<<<24, 256>>>(adaln1_b, adaln2_b, adb);
    k_cvt<<<512,  256>>>(inproj_w, winp,  L_*768*256);
    k_cvt<<<512,  256>>>(outproj_w,wout,  L_*256*256);
    k_cvt<<<1024, 256>>>(ff1_w,    wff1,  L_*1024*256);
    k_cvt<<<1024, 256>>>(ff2_w,    wff2,  L_*256*1024);
    k_cvt<<<256,  256>>>(fm_w2,    wfm2,  512*512);
    k_padw<<<512, KP_>>>(fm_w1, wfm1);

    // canvas encoder (streaming kernel; K=384/512)
    gemm_tc<1,1><<<dim3(4,  64), 256, GSMEM>>>(canvb, wce1, ce_b1, f1b, nullptr, B_, 512, 384);
    gemm_tc<0,1><<<dim3(2,  64), 256, GSMEM>>>(f1b,   wce2, ce_b2, cb,  nullptr, B_, 256, 512);

    // all 12 adaLN projections in one persistent GEMM: ss[B, 6144]
    gemm_pw<0,0><<<48*6, 256, GSMEM2>>>(cb, wad, adb, ss, nullptr, B_, NAD_, 48);

    // stroke projection
    k_stroke<<<BT_, 256>>>(strokes, sp_w, sp_b, pos_emb, xb);

    for (int l = 0; l < L_; l++) {
        k_modln<<<BT_/8, 256>>>(xb, ss, x2b, l*512);
        gemm_pw<0,1><<<6*49, 256, GSMEM2>>>(x2b, winp + (size_t)l*768*256,
                                            inproj_b + l*768, hb, nullptr, BT_, 768, 6);
        k_attn<<<B_, 256, ASMEM>>>(hb, x2b);
        gemm_pw<2,1><<<2*148, 256, GSMEM2>>>(x2b, wout + (size_t)l*256*256,
                                             outproj_b + l*256, xb, xb, BT_, 256, 2);
        k_modln<<<BT_/8, 256>>>(xb, ss, x2b, 3072 + l*512);
        gemm_pw<1,1><<<8*37, 256, GSMEM2>>>(x2b, wff1 + (size_t)l*1024*256,
                                            ff1_b + l*1024, hb, nullptr, BT_, 1024, 8);
        gemm_tc<2,1><<<dim3(2, 1920), 256, GSMEM>>>(hb, wff2 + (size_t)l*256*1024,
                                                    ff2_b + l*256, xb, xb, BT_, 256, 1024);
    }

    // output head
    k_head<<<B_/8, 256>>>(xb, on_g, on_b, a_tar, a_src, t_in, xinb, u);
    gemm_tc<1,1><<<dim3(4, 64), 256, GSMEM>>>(xinb, wfm1, fm_b1, f1b, nullptr, B_, 512, KP_);
    gemm_tc<1,1><<<dim3(4, 64), 256, GSMEM>>>(f1b,  wfm2, fm_b2, f2b, nullptr, B_, 512, 512);
    k_fm3<<<B_/8, 256>>>(f2b, fm_w3, fm_b3, u, part);
    k_reduce<<<1, 1024>>>(part, out);
}

// round 13
// speedup vs baseline: 1.0092x; 1.0092x over previous
#include <cuda_runtime.h>
#include <cuda_bf16.h>
#include <cstdint>
#include <math.h>

#define B_    8192
#define T_    30
#define D_    256
#define H_    8
#define L_    6
#define SD_   8
#define FF_   1024
#define CF_   256
#define BT_   (B_*T_)
#define KP_   320   // 296 padded to multiple of 64
#define NAD_  6144  // 12 * 512 batched adaLN output width

// ============================ ptx helpers ============================
#define SWZ(x) ((x) ^ (((x) >> 3) & 0x70))

static __device__ __forceinline__ uint32_t s2u(const void* p){
    uint32_t a;
    asm("{ .reg .u64 t; cvta.to.shared.u64 t, %1; cvt.u32.u64 %0, t; }" : "=r"(a) : "l"(p));
    return a;
}
static __device__ __forceinline__ void cpa16(uint32_t s, const void* g){
    asm volatile("cp.async.cg.shared.global [%0], [%1], 16;" :: "r"(s), "l"(g));
}
#define CP_COMMIT() asm volatile("cp.async.commit_group;" ::: "memory")
#define CP_WAIT1()  asm volatile("cp.async.wait_group 1;" ::: "memory")
#define CP_WAIT0()  asm volatile("cp.async.wait_group 0;" ::: "memory")

static __device__ __forceinline__ void ldm4(uint32_t a, uint32_t* r){
    asm volatile("ldmatrix.sync.aligned.m8n8.x4.shared.b16 {%0,%1,%2,%3}, [%4];"
        : "=r"(r[0]), "=r"(r[1]), "=r"(r[2]), "=r"(r[3]) : "r"(a));
}
static __device__ __forceinline__ void mma16816(float* d,
    uint32_t a0, uint32_t a1, uint32_t a2, uint32_t a3, uint32_t b0, uint32_t b1){
    asm volatile(
        "mma.sync.aligned.m16n8k16.row.col.f32.bf16.bf16.f32 "
        "{%0,%1,%2,%3}, {%4,%5,%6,%7}, {%8,%9}, {%0,%1,%2,%3};"
        : "+f"(d[0]), "+f"(d[1]), "+f"(d[2]), "+f"(d[3])
        : "r"(a0), "r"(a1), "r"(a2), "r"(a3), "r"(b0), "r"(b1));
}

// ============================ scratch ============================
__device__ float g_ss [(size_t)B_*NAD_];   // batched adaLN outputs
__device__ float g_adb[NAD_];              // concatenated adaLN biases
__device__ float g_u  [B_*SD_];
__device__ float g_part[1024];
__device__ __align__(256) __nv_bfloat16 g_xb [(size_t)BT_*D_];   // residual stream (bf16)
__device__ __align__(256) __nv_bfloat16 g_x2b[(size_t)BT_*D_];
__device__ __align__(256) __nv_bfloat16 g_hb [(size_t)BT_*FF_];
__device__ __align__(256) __nv_bfloat16 g_cb [B_*CF_];
__device__ __align__(256) __nv_bfloat16 g_canvb[B_*384];
__device__ __align__(256) __nv_bfloat16 g_f1b[B_*512];
__device__ __align__(256) __nv_bfloat16 g_f2b[B_*512];
__device__ __align__(256) __nv_bfloat16 g_xinb[B_*KP_];
__device__ __align__(256) __nv_bfloat16 g_wce1[512*384];
__device__ __align__(256) __nv_bfloat16 g_wce2[256*512];
__device__ __align__(256) __nv_bfloat16 g_wad [NAD_*256];
__device__ __align__(256) __nv_bfloat16 g_winp[L_*768*256];
__device__ __align__(256) __nv_bfloat16 g_wout[L_*256*256];
__device__ __align__(256) __nv_bfloat16 g_wff1[(size_t)L_*1024*256];
__device__ __align__(256) __nv_bfloat16 g_wff2[(size_t)L_*256*1024];
__device__ __align__(256) __nv_bfloat16 g_wfm1[512*KP_];
__device__ __align__(256) __nv_bfloat16 g_wfm2[512*512];

// ============================ streaming bf16 HMMA GEMM (R10 ordering) ============================
// C[M,N] = A[M,K] @ W[N,K]^T + bias.  EPI: 0 none, 1 silu, 2 +res(bf16)
// 128x128 tile, BK=64, 3 smem stages (96KB) -> 2 CTAs/SM.
// Mainloop: CP_WAIT1 (own groups: chunk i complete) -> __syncthreads (cross-thread
// visibility + stage reuse) -> issue i+2 -> commit -> compute i.
#define GSMEM (3*32768 + 1024)

static __device__ __forceinline__ void load_stage(
    uint32_t ab, int s, const __nv_bfloat16* A, const __nv_bfloat16* W,
    int K, int bm, int bn, int k0, int tid)
{
    uint32_t as_ = ab + s*32768;
    uint32_t bs_ = as_ + 16384;
    const __nv_bfloat16* Ap = A + (size_t)bm*K + k0;
    const __nv_bfloat16* Wp = W + (size_t)bn*K + k0;
#pragma unroll
    for (int t = 0; t < 4; t++) {
        int idx = tid + t*256;
        int row = idx >> 3, c16 = idx & 7;
        uint32_t off = (uint32_t)(row*128 + c16*16);
        cpa16(as_ + SWZ(off), Ap + (size_t)row*K + c16*8);
    }
#pragma unroll
    for (int t = 0; t < 4; t++) {
        int idx = tid + t*256;
        int row = idx >> 3, c16 = idx & 7;
        uint32_t off = (uint32_t)(row*128 + c16*16);
        cpa16(bs_ + SWZ(off), Wp + (size_t)row*K + c16*8);
    }
}

template<int EPI, int OUTBF>
__global__ __launch_bounds__(256, 2)
void gemm_tc(const __nv_bfloat16* __restrict__ A, const __nv_bfloat16* __restrict__ W,
             const float* __restrict__ bias, void* __restrict__ Cout,
             const void* __restrict__ res, int M, int N, int K)
{
    extern __shared__ char smem[];
    const int tid = threadIdx.x;
    uint32_t sraw = s2u(smem);
    uint32_t ab = (sraw + 1023) & ~1023u;
    char* smemc = smem + (ab - sraw);
    const int bm = blockIdx.y * 128;
    const int bn = blockIdx.x * 128;
    const int lane = tid & 31, wid = tid >> 5;
    const int wm = (wid & 3) * 32;
    const int wn = (wid >> 2) * 64;

    float acc[2][8][4];
#pragma unroll
    for (int a = 0; a < 2; a++)
#pragma unroll
        for (int b = 0; b < 8; b++)
#pragma unroll
            for (int c = 0; c < 4; c++) acc[a][b][c] = 0.f;

    const int nch = K >> 6;
    load_stage(ab, 0, A, W, K, bm, bn, 0,  tid); CP_COMMIT();
    load_stage(ab, 1, A, W, K, bm, bn, 64, tid); CP_COMMIT();

    const int r16 = lane & 15;
    const uint32_t cg = (uint32_t)((lane >> 4) << 4);

    int s = 0;
    for (int i = 0; i < nch; i++) {
        CP_WAIT1();        // own groups: chunk i complete (i+1 may be in flight)
        __syncthreads();   // cross-thread completion visibility + stage reuse guard
        if (i + 2 < nch) {
            int s2 = s + 2; if (s2 >= 3) s2 -= 3;
            load_stage(ab, s2, A, W, K, bm, bn, (i+2)*64, tid);
        }
        CP_COMMIT();

        const uint32_t as_ = ab + s*32768;
        const uint32_t bs_ = as_ + 16384;
#pragma unroll
        for (int k16 = 0; k16 < 4; k16++) {
            uint32_t af[2][4], bfr[4][4];
#pragma unroll
            for (int mt = 0; mt < 2; mt++) {
                uint32_t off = (uint32_t)((wm + mt*16 + r16)*128 + k16*32) + cg;
                ldm4(as_ + SWZ(off), af[mt]);
            }
#pragma unroll
            for (int nt2 = 0; nt2 < 4; nt2++) {
                uint32_t off = (uint32_t)((wn + nt2*16 + r16)*128 + k16*32) + cg;
                ldm4(bs_ + SWZ(off), bfr[nt2]);
            }
#pragma unroll
            for (int mt = 0; mt < 2; mt++)
#pragma unroll
                for (int nt2 = 0; nt2 < 4; nt2++) {
                    mma16816(acc[mt][nt2*2],   af[mt][0], af[mt][1], af[mt][2], af[mt][3],
                             bfr[nt2][0], bfr[nt2][2]);
                    mma16816(acc[mt][nt2*2+1], af[mt][0], af[mt][1], af[mt][2], af[mt][3],
                             bfr[nt2][1], bfr[nt2][3]);
                }
        }
        if (++s >= 3) s = 0;
    }
    CP_WAIT0();
    __syncthreads();

    // epilogue: regs -> smem (stride 132) -> coalesced fused stores
    float* smemT = (float*)smemc;
    {
        const int r4 = lane >> 2;
        const int c2 = (lane & 3) << 1;
#pragma unroll
        for (int mt = 0; mt < 2; mt++)
#pragma unroll
            for (int nt = 0; nt < 8; nt++) {
                int row = wm + mt*16 + r4;
                int col = wn + nt*8 + c2;
                *(float2*)&smemT[row*132 + col]     = make_float2(acc[mt][nt][0], acc[mt][nt][1]);
                *(float2*)&smemT[(row+8)*132 + col] = make_float2(acc[mt][nt][2], acc[mt][nt][3]);
            }
    }
    __syncthreads();
#pragma unroll
    for (int it = 0; it < 16; it++) {
        int idx = tid + it*256;
        int row = idx >> 5;
        int c4  = (idx & 31) << 2;
        float4 v = *(float4*)&smemT[row*132 + c4];
        float4 bb = *(const float4*)&bias[bn + c4];
        v.x += bb.x; v.y += bb.y; v.z += bb.z; v.w += bb.w;
        if (EPI == 1) {
            v.x *= 1.f/(1.f + __expf(-v.x));
            v.y *= 1.f/(1.f + __expf(-v.y));
            v.z *= 1.f/(1.f + __expf(-v.z));
            v.w *= 1.f/(1.f + __expf(-v.w));
        }
        size_t g = (size_t)(bm + row)*N + bn + c4;
        if (EPI == 2) {
            uint2 rr = *(const uint2*)((const __nv_bfloat16*)res + g);
            __nv_bfloat162 r0 = *(__nv_bfloat162*)&rr.x;
            __nv_bfloat162 r1 = *(__nv_bfloat162*)&rr.y;
            v.x += __bfloat162float(r0.x); v.y += __bfloat162float(r0.y);
            v.z += __bfloat162float(r1.x); v.w += __bfloat162float(r1.y);
        }
        if (OUTBF) {
            __nv_bfloat162 p0 = __floats2bfloat162_rn(v.x, v.y);
            __nv_bfloat162 p1 = __floats2bfloat162_rn(v.z, v.w);
            uint2 u2;
            u2.x = *(uint32_t*)&p0; u2.y = *(uint32_t*)&p1;
            *(uint2*)((__nv_bfloat16*)Cout + g) = u2;
        } else {
            *(float4*)((float*)Cout + g) = v;
        }
    }
}

// ============================ aux kernels ============================
__global__ void k_cvt(const float* __restrict__ s, __nv_bfloat16* __restrict__ d, int n)
{
    for (int i = blockIdx.x*blockDim.x + threadIdx.x; i < n; i += gridDim.x*blockDim.x)
        d[i] = __float2bfloat16(s[i]);
}

__global__ void k_cat(const float* __restrict__ b1, const float* __restrict__ b2,
                      float* __restrict__ d)
{
    int i = blockIdx.x*blockDim.x + threadIdx.x;   // 6144 total
    d[i] = (i < 3072) ? b1[i] : b2[i - 3072];
}

__global__ __launch_bounds__(256)
void k_stroke(const float* __restrict__ strokes, const float* __restrict__ sp_w,
              const float* __restrict__ sp_b, const float* __restrict__ pos,
              __nv_bfloat16* __restrict__ x)
{
    int row = blockIdx.x;
    int t = row % T_;
    int d = threadIdx.x;
    float acc = sp_b[d] + pos[t*D_ + d];
#pragma unroll
    for (int j = 0; j < 8; j++)
        acc += strokes[(size_t)row*8 + j] * sp_w[d*8 + j];
    x[(size_t)row*D_ + d] = __float2bfloat16(acc);
}

static __device__ __forceinline__ void unp8(uint4 u, float* v){
    __nv_bfloat162 p0 = *(__nv_bfloat162*)&u.x;
    __nv_bfloat162 p1 = *(__nv_bfloat162*)&u.y;
    __nv_bfloat162 p2 = *(__nv_bfloat162*)&u.z;
    __nv_bfloat162 p3 = *(__nv_bfloat162*)&u.w;
    v[0] = __bfloat162float(p0.x); v[1] = __bfloat162float(p0.y);
    v[2] = __bfloat162float(p1.x); v[3] = __bfloat162float(p1.y);
    v[4] = __bfloat162float(p2.x); v[5] = __bfloat162float(p2.y);
    v[6] = __bfloat162float(p3.x); v[7] = __bfloat162float(p3.y);
}

// warp-per-row adaLN modulate
__global__ __launch_bounds__(256)
void k_modln(const __nv_bfloat16* __restrict__ x, const float* __restrict__ ss,
             __nv_bfloat16* __restrict__ x2, int off)
{
    int w = threadIdx.x >> 5, ln = threadIdx.x & 31;
    int row = blockIdx.x*8 + w;
    int b = row / T_;
    float v[8];
    unp8(*(const uint4*)(x + (size_t)row*D_ + ln*8), v);
    float s = 0.f, q = 0.f;
#pragma unroll
    for (int j = 0; j < 8; j++) { s += v[j]; q += v[j]*v[j]; }
#pragma unroll
    for (int o = 16; o; o >>= 1) {
        s += __shfl_xor_sync(0xffffffffu, s, o);
        q += __shfl_xor_sync(0xffffffffu, q, o);
    }
    float mean = s * (1.f/256.f);
    float rstd = rsqrtf(q * (1.f/256.f) - mean*mean + 1e-5f);
    const float* ssb = ss + (size_t)b*NAD_ + off;
    float sc[8], sh[8];
    *(float4*)&sc[0] = *(const float4*)&ssb[ln*8];
    *(float4*)&sc[4] = *(const float4*)&ssb[ln*8 + 4];
    *(float4*)&sh[0] = *(const float4*)&ssb[256 + ln*8];
    *(float4*)&sh[4] = *(const float4*)&ssb[256 + ln*8 + 4];
    float o8[8];
#pragma unroll
    for (int j = 0; j < 8; j++)
        o8[j] = (1.f + sc[j])*((v[j] - mean)*rstd) + sh[j];
    __nv_bfloat162 p0 = __floats2bfloat162_rn(o8[0], o8[1]);
    __nv_bfloat162 p1 = __floats2bfloat162_rn(o8[2], o8[3]);
    __nv_bfloat162 p2 = __floats2bfloat162_rn(o8[4], o8[5]);
    __nv_bfloat162 p3 = __floats2bfloat162_rn(o8[6], o8[7]);
    uint4 u4;
    u4.x = *(uint32_t*)&p0; u4.y = *(uint32_t*)&p1;
    u4.z = *(uint32_t*)&p2; u4.w = *(uint32_t*)&p3;
    *(uint4*)&x2[(size_t)row*D_ + ln*8] = u4;
}

// ============================ attention ============================
// One CTA per batch element; K/V staged as bf16 pairs (30KB smem -> high occupancy).
// One warp per head, one lane per query; smem reads are broadcasts.
#define ASMEM (2*T_*128*4)   // 30720
__global__ __launch_bounds__(256)
void k_attn(const __nv_bfloat16* __restrict__ qkv, __nv_bfloat16* __restrict__ o)
{
    extern __shared__ uint32_t att[];
    uint32_t* ks = att;              // [T_][128] bf16x2 pairs
    uint32_t* vs = att + T_*128;
    int b = blockIdx.x;
    int tid = threadIdx.x;
    int h = tid >> 5, ln = tid & 31;

    // cooperative staging (bf16x2 copies, coalesced): 3840 u32 per array
#pragma unroll
    for (int it = 0; it < T_/2; it++) {
        int i = tid + it*256;
        int t = i >> 7, d2 = i & 127;
        size_t base = ((size_t)(b*T_ + t))*384 + d2;   // u32 view: 768 bf16 = 384 u32
        const uint32_t* q32 = (const uint32_t*)qkv;
        ks[t*128 + d2] = q32[base + 128];
        vs[t*128 + d2] = q32[base + 256];
    }
    __syncthreads();

    if (ln < T_) {
        const int q = ln;
        float qreg[32];
        const __nv_bfloat16* qp = qkv + ((size_t)(b*T_ + q))*768 + h*32;
#pragma unroll
        for (int d4 = 0; d4 < 4; d4++) {
            float v8[8];
            unp8(*(const uint4*)(qp + d4*8), v8);
#pragma unroll
            for (int j = 0; j < 8; j++) qreg[d4*8 + j] = v8[j];
        }
        const uint32_t* kh = ks + h*16;
        const uint32_t* vh = vs + h*16;
        const float scale = 0.17677669529663687f;

        float sc[T_];
#pragma unroll
        for (int k = 0; k < T_; k++) {
            float acc = 0.f;
#pragma unroll
            for (int d2 = 0; d2 < 16; d2++) {
                uint32_t pr = kh[k*128 + d2];
                __nv_bfloat162 p = *(__nv_bfloat162*)&pr;
                acc += qreg[d2*2]   * __bfloat162float(p.x);
                acc += qreg[d2*2+1] * __bfloat162float(p.y);
            }
            sc[k] = (k <= q) ? acc*scale : -1e30f;
        }
        float mx = -1e30f;
#pragma unroll
        for (int k = 0; k < T_; k++) mx = fmaxf(mx, sc[k]);
        float sm = 0.f;
#pragma unroll
        for (int k = 0; k < T_; k++) { sc[k] = __expf(sc[k] - mx); sm += sc[k]; }
        float inv = 1.f/sm;

        float o32[32];
#pragma unroll
        for (int d = 0; d < 32; d++) o32[d] = 0.f;
#pragma unroll
        for (int k = 0; k < T_; k++) {
            if (k <= q) {
                float a = sc[k]*inv;
#pragma unroll
                for (int d2 = 0; d2 < 16; d2++) {
                    uint32_t pr = vh[k*128 + d2];
                    __nv_bfloat162 p = *(__nv_bfloat162*)&pr;
                    o32[d2*2]   += a*__bfloat162float(p.x);
                    o32[d2*2+1] += a*__bfloat162float(p.y);
                }
            }
        }
        __nv_bfloat16* op = o + ((size_t)(b*T_ + q))*256 + h*32;
#pragma unroll
        for (int d4 = 0; d4 < 4; d4++) {
            __nv_bfloat162 p0 = __floats2bfloat162_rn(o32[d4*8+0], o32[d4*8+1]);
            __nv_bfloat162 p1 = __floats2bfloat162_rn(o32[d4*8+2], o32[d4*8+3]);
            __nv_bfloat162 p2 = __floats2bfloat162_rn(o32[d4*8+4], o32[d4*8+5]);
            __nv_bfloat162 p3 = __floats2bfloat162_rn(o32[d4*8+6], o32[d4*8+7]);
            uint4 u4;
            u4.x = *(uint32_t*)&p0; u4.y = *(uint32_t*)&p1;
            u4.z = *(uint32_t*)&p2; u4.w = *(uint32_t*)&p3;
            *(uint4*)(op + d4*8) = u4;
        }
    }
}

// fused head: final LN on last token + xin tail + u
__global__ __launch_bounds__(256)
void k_head(const __nv_bfloat16* __restrict__ x, const float* __restrict__ g,
            const float* __restrict__ be, const float* __restrict__ a_tar,
            const float* __restrict__ a_src, const float* __restrict__ t,
            __nv_bfloat16* __restrict__ xin, float* __restrict__ u)
{
    int w = threadIdx.x >> 5, ln = threadIdx.x & 31;
    int b = blockIdx.x*8 + w;
    float v[8];
    unp8(*(const uint4*)(x + ((size_t)(b*T_ + T_ - 1))*D_ + ln*8), v);
    float s = 0.f, q = 0.f;
#pragma unroll
    for (int j = 0; j < 8; j++) { s += v[j]; q += v[j]*v[j]; }
#pragma unroll
    for (int o = 16; o; o >>= 1) {
        s += __shfl_xor_sync(0xffffffffu, s, o);
        q += __shfl_xor_sync(0xffffffffu, q, o);
    }
    float mean = s * (1.f/256.f);
    float rstd = rsqrtf(q * (1.f/256.f) - mean*mean + 1e-5f);
    size_t base = (size_t)b*KP_;
#pragma unroll
    for (int j = 0; j < 8; j++) {
        int d = ln*8 + j;
        xin[base + d] = __float2bfloat16(((v[j] - mean)*rstd)*g[d] + be[d]);
    }
    float tb = t[b];
    if (ln < 8) {
        float as = a_src[b*8+ln], at = a_tar[b*8+ln];
        xin[base + 256 + ln] = __float2bfloat16((1.f - tb)*as + tb*at);
        u[b*8+ln] = at - as;
    } else if (ln < 24) {
        int j = ln - 8;
        float freq = __expf(-9.210340371976184f * (float)j / 15.f);
        float arg = tb * freq;
        xin[base + 264 + j] = __float2bfloat16(sinf(arg));
        xin[base + 280 + j] = __float2bfloat16(cosf(arg));
    } else {
        int j0 = (ln - 24) * 3;
#pragma unroll
        for (int k = 0; k < 3; k++)
            xin[base + 296 + j0 + k] = __float2bfloat16(0.f);
    }
}

__global__ void k_padw(const float* __restrict__ w, __nv_bfloat16* __restrict__ wp)
{
    int n = blockIdx.x, k = threadIdx.x;
    wp[n*KP_ + k] = __float2bfloat16(k < 296 ? w[n*296 + k] : 0.f);
}

__global__ __launch_bounds__(256)
void k_fm3(const __nv_bfloat16* __restrict__ f2, const float* __restrict__ w3,
           const float* __restrict__ b3, const float* __restrict__ u,
           float* __restrict__ part)
{
    __shared__ float sp[8];
    int w = threadIdx.x >> 5, ln = threadIdx.x & 31;
    int b = blockIdx.x * 8 + w;
    float lsum = 0.f;
    const __nv_bfloat16* fr = f2 + (size_t)b*512;
#pragma unroll
    for (int n = 0; n < 8; n++) {
        const float* wr = w3 + n*512;
        float p = 0.f;
        for (int k = ln; k < 512; k += 32) p += __bfloat162float(fr[k])*wr[k];
#pragma unroll
        for (int o = 16; o; o >>= 1) p += __shfl_xor_sync(0xffffffffu, p, o);
        if (ln == 0) {
            float d = p + b3[n] - u[b*8+n];
            lsum += d*d;
        }
    }
    if (ln == 0) sp[w] = lsum;
    __syncthreads();
    if (threadIdx.x == 0) {
        float s = 0.f;
        for (int i = 0; i < 8; i++) s += sp[i];
        part[blockIdx.x] = s;
    }
}

__global__ void k_reduce(const float* __restrict__ part, float* __restrict__ out)
{
    __shared__ float sp[1024];
    int i = threadIdx.x;
    sp[i] = part[i];
    __syncthreads();
    for (int s = 512; s; s >>= 1) { if (i < s) sp[i] += sp[i+s]; __syncthreads(); }
    if (i == 0) out[0] = sp[0] * (1.f / (float)(B_*SD_));
}

// ============================ launch ============================
extern "C" void kernel_launch(void* const* d_in, const int* in_sizes, int n_in,
                              void* d_out, int out_size)
{
    const float* strokes  = (const float*)d_in[0];
    const float* canvas   = (const float*)d_in[1];
    const float* a_tar    = (const float*)d_in[2];
    const float* a_src    = (const float*)d_in[3];
    const float* t_in     = (const float*)d_in[4];
    const float* ce_w1    = (const float*)d_in[5];
    const float* ce_b1    = (const float*)d_in[6];
    const float* ce_w2    = (const float*)d_in[7];
    const float* ce_b2    = (const float*)d_in[8];
    const float* sp_w     = (const float*)d_in[9];
    const float* sp_b     = (const float*)d_in[10];
    const float* pos_emb  = (const float*)d_in[11];
    const float* adaln1_w = (const float*)d_in[12];
    const float* adaln1_b = (const float*)d_in[13];
    const float* inproj_w = (const float*)d_in[14];
    const float* inproj_b = (const float*)d_in[15];
    const float* outproj_w= (const float*)d_in[16];
    const float* outproj_b= (const float*)d_in[17];
    const float* adaln2_w = (const float*)d_in[18];
    const float* adaln2_b = (const float*)d_in[19];
    const float* ff1_w    = (const float*)d_in[20];
    const float* ff1_b    = (const float*)d_in[21];
    const float* ff2_w    = (const float*)d_in[22];
    const float* ff2_b    = (const float*)d_in[23];
    const float* on_g     = (const float*)d_in[24];
    const float* on_b     = (const float*)d_in[25];
    const float* fm_w1    = (const float*)d_in[26];
    const float* fm_b1    = (const float*)d_in[27];
    const float* fm_w2    = (const float*)d_in[28];
    const float* fm_b2    = (const float*)d_in[29];
    const float* fm_w3    = (const float*)d_in[30];
    const float* fm_b3    = (const float*)d_in[31];
    float* out = (float*)d_out;

    float *ss, *adb, *u, *part;
    __nv_bfloat16 *xb, *x2b, *hb, *cb, *canvb, *f1b, *f2b, *xinb;
    __nv_bfloat16 *wce1, *wce2, *wad, *winp, *wout, *wff1, *wff2, *wfm1, *wfm2;
    cudaGetSymbolAddress((void**)&ss,   g_ss);
    cudaGetSymbolAddress((void**)&adb,  g_adb);
    cudaGetSymbolAddress((void**)&u,    g_u);
    cudaGetSymbolAddress((void**)&part, g_part);
    cudaGetSymbolAddress((void**)&xb,   g_xb);
    cudaGetSymbolAddress((void**)&x2b,  g_x2b);
    cudaGetSymbolAddress((void**)&hb,   g_hb);
    cudaGetSymbolAddress((void**)&cb,   g_cb);
    cudaGetSymbolAddress((void**)&canvb,g_canvb);
    cudaGetSymbolAddress((void**)&f1b,  g_f1b);
    cudaGetSymbolAddress((void**)&f2b,  g_f2b);
    cudaGetSymbolAddress((void**)&xinb, g_xinb);
    cudaGetSymbolAddress((void**)&wce1, g_wce1);
    cudaGetSymbolAddress((void**)&wce2, g_wce2);
    cudaGetSymbolAddress((void**)&wad,  g_wad);
    cudaGetSymbolAddress((void**)&winp, g_winp);
    cudaGetSymbolAddress((void**)&wout, g_wout);
    cudaGetSymbolAddress((void**)&wff1, g_wff1);
    cudaGetSymbolAddress((void**)&wff2, g_wff2);
    cudaGetSymbolAddress((void**)&wfm1, g_wfm1);
    cudaGetSymbolAddress((void**)&wfm2, g_wfm2);

    cudaFuncSetAttribute(gemm_tc<0,0>, cudaFuncAttributeMaxDynamicSharedMemorySize, GSMEM);
    cudaFuncSetAttribute(gemm_tc<0,1>, cudaFuncAttributeMaxDynamicSharedMemorySize, GSMEM);
    cudaFuncSetAttribute(gemm_tc<1,1>, cudaFuncAttributeMaxDynamicSharedMemorySize, GSMEM);
    cudaFuncSetAttribute(gemm_tc<2,1>, cudaFuncAttributeMaxDynamicSharedMemorySize, GSMEM);
    cudaFuncSetAttribute(k_attn,       cudaFuncAttributeMaxDynamicSharedMemorySize, ASMEM);

    // launches 1-5: minimal deps for the canvas GEMM (so launch #6, the ncu
    // capture target [-s 5 -c 1], is a representative streaming GEMM)
    k_cvt<<<1024, 256>>>(canvas,   canvb, B_*384);
    k_cvt<<<256,  256>>>(ce_w1,    wce1,  512*384);
    k_cvt<<<256,  256>>>(ce_w2,    wce2,  256*512);
    k_cat<<<24, 256>>>(adaln1_b, adaln2_b, adb);
    k_padw<<<512, KP_>>>(fm_w1, wfm1);

    // launch #6: canvas encoder GEMM (profiled)
    gemm_tc<1,1><<<dim3(4,  64), 256, GSMEM>>>(canvb, wce1, ce_b1, f1b, nullptr, B_, 512, 384);
    gemm_tc<0,1><<<dim3(2,  64), 256, GSMEM>>>(f1b,   wce2, ce_b2, cb,  nullptr, B_, 256, 512);

    // remaining weight conversions
    k_cvt<<<512,  256>>>(adaln1_w, wad,             L_*512*256);
    k_cvt<<<512,  256>>>(adaln2_w, wad + 3072*256,  L_*512*256);
    k_cvt<<<512,  256>>>(inproj_w, winp,  L_*768*256);
    k_cvt<<<512,  256>>>(outproj_w,wout,  L_*256*256);
    k_cvt<<<1024, 256>>>(ff1_w,    wff1,  L_*1024*256);
    k_cvt<<<1024, 256>>>(ff2_w,    wff2,  L_*256*1024);
    k_cvt<<<256,  256>>>(fm_w2,    wfm2,  512*512);

    // all 12 adaLN projections in one batched GEMM: ss[B, 6144]
    gemm_tc<0,0><<<dim3(48, 64), 256, GSMEM>>>(cb, wad, adb, ss, nullptr, B_, NAD_, 256);

    // stroke projection
    k_stroke<<<BT_, 256>>>(strokes, sp_w, sp_b, pos_emb, xb);

    for (int l = 0; l < L_; l++) {
        k_modln<<<BT_/8, 256>>>(xb, ss, x2b, l*512);
        gemm_tc<0,1><<<dim3(6, 1920), 256, GSMEM>>>(x2b, winp + (size_t)l*768*256,
                                                    inproj_b + l*768, hb, nullptr, BT_, 768, 256);
        k_attn<<<B_, 256, ASMEM>>>(hb, x2b);
        gemm_tc<2,1><<<dim3(2, 1920), 256, GSMEM>>>(x2b, wout + (size_t)l*256*256,
                                                    outproj_b + l*256, xb, xb, BT_, 256, 256);
        k_modln<<<BT_/8, 256>>>(xb, ss, x2b, 3072 + l*512);
        gemm_tc<1,1><<<dim3(8, 1920), 256, GSMEM>>>(x2b, wff1 + (size_t)l*1024*256,
                                                    ff1_b + l*1024, hb, nullptr, BT_, 1024, 256);
        gemm_tc<2,1><<<dim3(2, 1920), 256, GSMEM>>>(hb, wff2 + (size_t)l*256*1024,
                                                    ff2_b + l*256, xb, xb, BT_, 256, 1024);
    }

    // output head
    k_head<<<B_/8, 256>>>(xb, on_g, on_b, a_tar, a_src, t_in, xinb, u);
    gemm_tc<1,1><<<dim3(4, 64), 256, GSMEM>>>(xinb, wfm1, fm_b1, f1b, nullptr, B_, 512, KP_);
    gemm_tc<1,1><<<dim3(4, 64), 256, GSMEM>>>(f1b,  wfm2, fm_b2, f2b, nullptr, B_, 512, 512);
    k_fm3<<<B_/8, 256>>>(f2b, fm_w3, fm_b3, u, part);
    k_reduce<<<1, 1024>>>(part, out);
}

// round 14
// speedup vs baseline: 1.0619x; 1.0522x over previous
#include <cuda_runtime.h>
#include <cuda_bf16.h>
#include <cstdint>
#include <math.h>

#define B_    8192
#define T_    30
#define D_    256
#define H_    8
#define L_    6
#define SD_   8
#define FF_   1024
#define CF_   256
#define BT_   (B_*T_)
#define KP_   320   // 296 padded to multiple of 64
#define NAD_  6144  // 12 * 512 batched adaLN output width

// ============================ ptx helpers ============================
#define SWZ(x) ((x) ^ (((x) >> 3) & 0x70))

static __device__ __forceinline__ uint32_t s2u(const void* p){
    uint32_t a;
    asm("{ .reg .u64 t; cvta.to.shared.u64 t, %1; cvt.u32.u64 %0, t; }" : "=r"(a) : "l"(p));
    return a;
}
static __device__ __forceinline__ void cpa16(uint32_t s, const void* g){
    asm volatile("cp.async.cg.shared.global [%0], [%1], 16;" :: "r"(s), "l"(g));
}
#define CP_COMMIT() asm volatile("cp.async.commit_group;" ::: "memory")
#define CP_WAIT1()  asm volatile("cp.async.wait_group 1;" ::: "memory")
#define CP_WAIT0()  asm volatile("cp.async.wait_group 0;" ::: "memory")

static __device__ __forceinline__ void ldm4(uint32_t a, uint32_t* r){
    asm volatile("ldmatrix.sync.aligned.m8n8.x4.shared.b16 {%0,%1,%2,%3}, [%4];"
        : "=r"(r[0]), "=r"(r[1]), "=r"(r[2]), "=r"(r[3]) : "r"(a));
}
static __device__ __forceinline__ void mma16816(float* d,
    uint32_t a0, uint32_t a1, uint32_t a2, uint32_t a3, uint32_t b0, uint32_t b1){
    asm volatile(
        "mma.sync.aligned.m16n8k16.row.col.f32.bf16.bf16.f32 "
        "{%0,%1,%2,%3}, {%4,%5,%6,%7}, {%8,%9}, {%0,%1,%2,%3};"
        : "+f"(d[0]), "+f"(d[1]), "+f"(d[2]), "+f"(d[3])
        : "r"(a0), "r"(a1), "r"(a2), "r"(a3), "r"(b0), "r"(b1));
}

// ============================ scratch ============================
__device__ float g_ss [(size_t)B_*NAD_];   // batched adaLN outputs
__device__ float g_adb[NAD_];              // concatenated adaLN biases
__device__ float g_u  [B_*SD_];
__device__ float g_part[1024];
__device__ __align__(256) __nv_bfloat16 g_xb [(size_t)BT_*D_];   // residual stream (bf16)
__device__ __align__(256) __nv_bfloat16 g_x2b[(size_t)BT_*D_];
__device__ __align__(256) __nv_bfloat16 g_hb [(size_t)BT_*FF_];
__device__ __align__(256) __nv_bfloat16 g_cb [B_*CF_];
__device__ __align__(256) __nv_bfloat16 g_canvb[B_*384];
__device__ __align__(256) __nv_bfloat16 g_f1b[B_*512];
__device__ __align__(256) __nv_bfloat16 g_f2b[B_*512];
__device__ __align__(256) __nv_bfloat16 g_xinb[B_*KP_];
__device__ __align__(256) __nv_bfloat16 g_wce1[512*384];
__device__ __align__(256) __nv_bfloat16 g_wce2[256*512];
__device__ __align__(256) __nv_bfloat16 g_wad [NAD_*256];
__device__ __align__(256) __nv_bfloat16 g_winp[L_*768*256];
__device__ __align__(256) __nv_bfloat16 g_wout[L_*256*256];
__device__ __align__(256) __nv_bfloat16 g_wff1[(size_t)L_*1024*256];
__device__ __align__(256) __nv_bfloat16 g_wff2[(size_t)L_*256*1024];
__device__ __align__(256) __nv_bfloat16 g_wfm1[512*KP_];
__device__ __align__(256) __nv_bfloat16 g_wfm2[512*512];

// ============================ streaming bf16 HMMA GEMM (R10) ============================
// C[M,N] = A[M,K] @ W[N,K]^T + bias.  EPI: 0 none, 1 silu, 2 +res(bf16)
// 128x128 tile, BK=64, 3 smem stages (96KB) -> 2 CTAs/SM, prefetch dist 2.
#define GSMEM (3*32768 + 1024)

static __device__ __forceinline__ void load_stage(
    uint32_t ab, int s, const __nv_bfloat16* A, const __nv_bfloat16* W,
    int K, int bm, int bn, int k0, int tid)
{
    uint32_t as_ = ab + s*32768;
    uint32_t bs_ = as_ + 16384;
    const __nv_bfloat16* Ap = A + (size_t)bm*K + k0;
    const __nv_bfloat16* Wp = W + (size_t)bn*K + k0;
#pragma unroll
    for (int t = 0; t < 4; t++) {
        int idx = tid + t*256;
        int row = idx >> 3, c16 = idx & 7;
        uint32_t off = (uint32_t)(row*128 + c16*16);
        cpa16(as_ + SWZ(off), Ap + (size_t)row*K + c16*8);
    }
#pragma unroll
    for (int t = 0; t < 4; t++) {
        int idx = tid + t*256;
        int row = idx >> 3, c16 = idx & 7;
        uint32_t off = (uint32_t)(row*128 + c16*16);
        cpa16(bs_ + SWZ(off), Wp + (size_t)row*K + c16*8);
    }
}

template<int EPI, int OUTBF>
__global__ __launch_bounds__(256, 2)
void gemm_tc(const __nv_bfloat16* __restrict__ A, const __nv_bfloat16* __restrict__ W,
             const float* __restrict__ bias, void* __restrict__ Cout,
             const void* __restrict__ res, int M, int N, int K)
{
    extern __shared__ char smem[];
    const int tid = threadIdx.x;
    uint32_t sraw = s2u(smem);
    uint32_t ab = (sraw + 1023) & ~1023u;
    char* smemc = smem + (ab - sraw);
    const int bm = blockIdx.y * 128;
    const int bn = blockIdx.x * 128;
    const int lane = tid & 31, wid = tid >> 5;
    const int wm = (wid & 3) * 32;
    const int wn = (wid >> 2) * 64;

    float acc[2][8][4];
#pragma unroll
    for (int a = 0; a < 2; a++)
#pragma unroll
        for (int b = 0; b < 8; b++)
#pragma unroll
            for (int c = 0; c < 4; c++) acc[a][b][c] = 0.f;

    const int nch = K >> 6;
    load_stage(ab, 0, A, W, K, bm, bn, 0,  tid); CP_COMMIT();
    load_stage(ab, 1, A, W, K, bm, bn, 64, tid); CP_COMMIT();

    const int r16 = lane & 15;
    const uint32_t cg = (uint32_t)((lane >> 4) << 4);

    int s = 0;
    for (int i = 0; i < nch; i++) {
        CP_WAIT1();
        __syncthreads();
        if (i + 2 < nch) {
            int s2 = s + 2; if (s2 >= 3) s2 -= 3;
            load_stage(ab, s2, A, W, K, bm, bn, (i+2)*64, tid);
        }
        CP_COMMIT();

        const uint32_t as_ = ab + s*32768;
        const uint32_t bs_ = as_ + 16384;
#pragma unroll
        for (int k16 = 0; k16 < 4; k16++) {
            uint32_t af[2][4], bfr[4][4];
#pragma unroll
            for (int mt = 0; mt < 2; mt++) {
                uint32_t off = (uint32_t)((wm + mt*16 + r16)*128 + k16*32) + cg;
                ldm4(as_ + SWZ(off), af[mt]);
            }
#pragma unroll
            for (int nt2 = 0; nt2 < 4; nt2++) {
                uint32_t off = (uint32_t)((wn + nt2*16 + r16)*128 + k16*32) + cg;
                ldm4(bs_ + SWZ(off), bfr[nt2]);
            }
#pragma unroll
            for (int mt = 0; mt < 2; mt++)
#pragma unroll
                for (int nt2 = 0; nt2 < 4; nt2++) {
                    mma16816(acc[mt][nt2*2],   af[mt][0], af[mt][1], af[mt][2], af[mt][3],
                             bfr[nt2][0], bfr[nt2][2]);
                    mma16816(acc[mt][nt2*2+1], af[mt][0], af[mt][1], af[mt][2], af[mt][3],
                             bfr[nt2][1], bfr[nt2][3]);
                }
        }
        if (++s >= 3) s = 0;
    }
    CP_WAIT0();
    __syncthreads();

    // epilogue: regs -> smem (stride 132) -> coalesced fused stores
    float* smemT = (float*)smemc;
    {
        const int r4 = lane >> 2;
        const int c2 = (lane & 3) << 1;
#pragma unroll
        for (int mt = 0; mt < 2; mt++)
#pragma unroll
            for (int nt = 0; nt < 8; nt++) {
                int row = wm + mt*16 + r4;
                int col = wn + nt*8 + c2;
                *(float2*)&smemT[row*132 + col]     = make_float2(acc[mt][nt][0], acc[mt][nt][1]);
                *(float2*)&smemT[(row+8)*132 + col] = make_float2(acc[mt][nt][2], acc[mt][nt][3]);
            }
    }
    __syncthreads();
#pragma unroll
    for (int it = 0; it < 16; it++) {
        int idx = tid + it*256;
        int row = idx >> 5;
        int c4  = (idx & 31) << 2;
        float4 v = *(float4*)&smemT[row*132 + c4];
        float4 bb = *(const float4*)&bias[bn + c4];
        v.x += bb.x; v.y += bb.y; v.z += bb.z; v.w += bb.w;
        if (EPI == 1) {
            v.x *= 1.f/(1.f + __expf(-v.x));
            v.y *= 1.f/(1.f + __expf(-v.y));
            v.z *= 1.f/(1.f + __expf(-v.z));
            v.w *= 1.f/(1.f + __expf(-v.w));
        }
        size_t g = (size_t)(bm + row)*N + bn + c4;
        if (EPI == 2) {
            uint2 rr = *(const uint2*)((const __nv_bfloat16*)res + g);
            __nv_bfloat162 r0 = *(__nv_bfloat162*)&rr.x;
            __nv_bfloat162 r1 = *(__nv_bfloat162*)&rr.y;
            v.x += __bfloat162float(r0.x); v.y += __bfloat162float(r0.y);
            v.z += __bfloat162float(r1.x); v.w += __bfloat162float(r1.y);
        }
        if (OUTBF) {
            __nv_bfloat162 p0 = __floats2bfloat162_rn(v.x, v.y);
            __nv_bfloat162 p1 = __floats2bfloat162_rn(v.z, v.w);
            uint2 u2;
            u2.x = *(uint32_t*)&p0; u2.y = *(uint32_t*)&p1;
            *(uint2*)((__nv_bfloat16*)Cout + g) = u2;
        } else {
            *(float4*)((float*)Cout + g) = v;
        }
    }
}

// ============================ aux kernels ============================
__global__ void k_cvt(const float* __restrict__ s, __nv_bfloat16* __restrict__ d, int n)
{
    for (int i = blockIdx.x*blockDim.x + threadIdx.x; i < n; i += gridDim.x*blockDim.x)
        d[i] = __float2bfloat16(s[i]);
}

__global__ void k_cat(const float* __restrict__ b1, const float* __restrict__ b2,
                      float* __restrict__ d)
{
    int i = blockIdx.x*blockDim.x + threadIdx.x;   // 6144 total
    d[i] = (i < 3072) ? b1[i] : b2[i - 3072];
}

__global__ __launch_bounds__(256)
void k_stroke(const float* __restrict__ strokes, const float* __restrict__ sp_w,
              const float* __restrict__ sp_b, const float* __restrict__ pos,
              __nv_bfloat16* __restrict__ x)
{
    int row = blockIdx.x;
    int t = row % T_;
    int d = threadIdx.x;
    float acc = sp_b[d] + pos[t*D_ + d];
#pragma unroll
    for (int j = 0; j < 8; j++)
        acc += strokes[(size_t)row*8 + j] * sp_w[d*8 + j];
    x[(size_t)row*D_ + d] = __float2bfloat16(acc);
}

static __device__ __forceinline__ void unp8(uint4 u, float* v){
    __nv_bfloat162 p0 = *(__nv_bfloat162*)&u.x;
    __nv_bfloat162 p1 = *(__nv_bfloat162*)&u.y;
    __nv_bfloat162 p2 = *(__nv_bfloat162*)&u.z;
    __nv_bfloat162 p3 = *(__nv_bfloat162*)&u.w;
    v[0] = __bfloat162float(p0.x); v[1] = __bfloat162float(p0.y);
    v[2] = __bfloat162float(p1.x); v[3] = __bfloat162float(p1.y);
    v[4] = __bfloat162float(p2.x); v[5] = __bfloat162float(p2.y);
    v[6] = __bfloat162float(p3.x); v[7] = __bfloat162float(p3.y);
}

// warp-per-row adaLN modulate
__global__ __launch_bounds__(256)
void k_modln(const __nv_bfloat16* __restrict__ x, const float* __restrict__ ss,
             __nv_bfloat16* __restrict__ x2, int off)
{
    int w = threadIdx.x >> 5, ln = threadIdx.x & 31;
    int row = blockIdx.x*8 + w;
    int b = row / T_;
    float v[8];
    unp8(*(const uint4*)(x + (size_t)row*D_ + ln*8), v);
    float s = 0.f, q = 0.f;
#pragma unroll
    for (int j = 0; j < 8; j++) { s += v[j]; q += v[j]*v[j]; }
#pragma unroll
    for (int o = 16; o; o >>= 1) {
        s += __shfl_xor_sync(0xffffffffu, s, o);
        q += __shfl_xor_sync(0xffffffffu, q, o);
    }
    float mean = s * (1.f/256.f);
    float rstd = rsqrtf(q * (1.f/256.f) - mean*mean + 1e-5f);
    const float* ssb = ss + (size_t)b*NAD_ + off;
    float sc[8], sh[8];
    *(float4*)&sc[0] = *(const float4*)&ssb[ln*8];
    *(float4*)&sc[4] = *(const float4*)&ssb[ln*8 + 4];
    *(float4*)&sh[0] = *(const float4*)&ssb[256 + ln*8];
    *(float4*)&sh[4] = *(const float4*)&ssb[256 + ln*8 + 4];
    float o8[8];
#pragma unroll
    for (int j = 0; j < 8; j++)
        o8[j] = (1.f + sc[j])*((v[j] - mean)*rstd) + sh[j];
    __nv_bfloat162 p0 = __floats2bfloat162_rn(o8[0], o8[1]);
    __nv_bfloat162 p1 = __floats2bfloat162_rn(o8[2], o8[3]);
    __nv_bfloat162 p2 = __floats2bfloat162_rn(o8[4], o8[5]);
    __nv_bfloat162 p3 = __floats2bfloat162_rn(o8[6], o8[7]);
    uint4 u4;
    u4.x = *(uint32_t*)&p0; u4.y = *(uint32_t*)&p1;
    u4.z = *(uint32_t*)&p2; u4.w = *(uint32_t*)&p3;
    *(uint4*)&x2[(size_t)row*D_ + ln*8] = u4;
}

// ============================ attention (R10 + Q staged through smem) ============================
// One CTA per batch element. K/V fp32 [T][256] (compute reads are warp broadcasts).
// Q staged per-head padded [h][t][33] so per-lane reads (lane = query) are
// conflict-free (stride 33). All global reads in the staging loop are coalesced.
#define QSTR 33
#define ASMEM (2*T_*256*4 + H_*T_*QSTR*4)   // 61440 + 31680 = 93120
__global__ __launch_bounds__(256)
void k_attn(const __nv_bfloat16* __restrict__ qkv, __nv_bfloat16* __restrict__ o)
{
    extern __shared__ float att[];
    float* ks = att;                 // [T_][256]
    float* vs = att + T_*256;        // [T_][256]
    float* qs = att + 2*T_*256;      // [H_][T_][QSTR]
    int b = blockIdx.x;
    int tid = threadIdx.x;
    int h = tid >> 5, ln = tid & 31;

    // cooperative staging: Q/K/V for all heads, coalesced global reads
#pragma unroll
    for (int it = 0; it < T_; it++) {
        int i = tid + it*256;
        int t = i >> 8, d = i & 255;
        size_t base = ((size_t)(b*T_ + t))*768 + d;
        int hh = d >> 5, dd = d & 31;
        qs[hh*(T_*QSTR) + t*QSTR + dd] = __bfloat162float(qkv[base]);
        ks[t*256 + d] = __bfloat162float(qkv[base + 256]);
        vs[t*256 + d] = __bfloat162float(qkv[base + 512]);
    }
    __syncthreads();

    if (ln < T_) {
        const int q = ln;
        float qreg[32];
        const float* qh = qs + h*(T_*QSTR) + q*QSTR;
#pragma unroll
        for (int d = 0; d < 32; d++) qreg[d] = qh[d];
        const float* kh = ks + h*32;
        const float* vh = vs + h*32;
        const float scale = 0.17677669529663687f;

        float sc[T_];
#pragma unroll
        for (int k = 0; k < T_; k++) {
            float acc = 0.f;
#pragma unroll
            for (int d = 0; d < 32; d++) acc += qreg[d]*kh[k*256 + d];
            sc[k] = (k <= q) ? acc*scale : -1e30f;
        }
        float mx = -1e30f;
#pragma unroll
        for (int k = 0; k < T_; k++) mx = fmaxf(mx, sc[k]);
        float sm = 0.f;
#pragma unroll
        for (int k = 0; k < T_; k++) { sc[k] = __expf(sc[k] - mx); sm += sc[k]; }
        float inv = 1.f/sm;

        float o32[32];
#pragma unroll
        for (int d = 0; d < 32; d++) o32[d] = 0.f;
#pragma unroll
        for (int k = 0; k < T_; k++) {
            float a = sc[k]*inv;
            if (k <= q) {
#pragma unroll
                for (int d = 0; d < 32; d++) o32[d] += a*vh[k*256 + d];
            }
        }
        __nv_bfloat16* op = o + ((size_t)(b*T_ + q))*256 + h*32;
#pragma unroll
        for (int d4 = 0; d4 < 4; d4++) {
            __nv_bfloat162 p0 = __floats2bfloat162_rn(o32[d4*8+0], o32[d4*8+1]);
            __nv_bfloat162 p1 = __floats2bfloat162_rn(o32[d4*8+2], o32[d4*8+3]);
            __nv_bfloat162 p2 = __floats2bfloat162_rn(o32[d4*8+4], o32[d4*8+5]);
            __nv_bfloat162 p3 = __floats2bfloat162_rn(o32[d4*8+6], o32[d4*8+7]);
            uint4 u4;
            u4.x = *(uint32_t*)&p0; u4.y = *(uint32_t*)&p1;
            u4.z = *(uint32_t*)&p2; u4.w = *(uint32_t*)&p3;
            *(uint4*)(op + d4*8) = u4;
        }
    }
}

// fused head: final LN on last token + xin tail + u
__global__ __launch_bounds__(256)
void k_head(const __nv_bfloat16* __restrict__ x, const float* __restrict__ g,
            const float* __restrict__ be, const float* __restrict__ a_tar,
            const float* __restrict__ a_src, const float* __restrict__ t,
            __nv_bfloat16* __restrict__ xin, float* __restrict__ u)
{
    int w = threadIdx.x >> 5, ln = threadIdx.x & 31;
    int b = blockIdx.x*8 + w;
    float v[8];
    unp8(*(const uint4*)(x + ((size_t)(b*T_ + T_ - 1))*D_ + ln*8), v);
    float s = 0.f, q = 0.f;
#pragma unroll
    for (int j = 0; j < 8; j++) { s += v[j]; q += v[j]*v[j]; }
#pragma unroll
    for (int o = 16; o; o >>= 1) {
        s += __shfl_xor_sync(0xffffffffu, s, o);
        q += __shfl_xor_sync(0xffffffffu, q, o);
    }
    float mean = s * (1.f/256.f);
    float rstd = rsqrtf(q * (1.f/256.f) - mean*mean + 1e-5f);
    size_t base = (size_t)b*KP_;
#pragma unroll
    for (int j = 0; j < 8; j++) {
        int d = ln*8 + j;
        xin[base + d] = __float2bfloat16(((v[j] - mean)*rstd)*g[d] + be[d]);
    }
    float tb = t[b];
    if (ln < 8) {
        float as = a_src[b*8+ln], at = a_tar[b*8+ln];
        xin[base + 256 + ln] = __float2bfloat16((1.f - tb)*as + tb*at);
        u[b*8+ln] = at - as;
    } else if (ln < 24) {
        int j = ln - 8;
        float freq = __expf(-9.210340371976184f * (float)j / 15.f);
        float arg = tb * freq;
        xin[base + 264 + j] = __float2bfloat16(sinf(arg));
        xin[base + 280 + j] = __float2bfloat16(cosf(arg));
    } else {
        int j0 = (ln - 24) * 3;
#pragma unroll
        for (int k = 0; k < 3; k++)
            xin[base + 296 + j0 + k] = __float2bfloat16(0.f);
    }
}

__global__ void k_padw(const float* __restrict__ w, __nv_bfloat16* __restrict__ wp)
{
    int n = blockIdx.x, k = threadIdx.x;
    wp[n*KP_ + k] = __float2bfloat16(k < 296 ? w[n*296 + k] : 0.f);
}

__global__ __launch_bounds__(256)
void k_fm3(const __nv_bfloat16* __restrict__ f2, const float* __restrict__ w3,
           const float* __restrict__ b3, const float* __restrict__ u,
           float* __restrict__ part)
{
    __shared__ float sp[8];
    int w = threadIdx.x >> 5, ln = threadIdx.x & 31;
    int b = blockIdx.x * 8 + w;
    float lsum = 0.f;
    const __nv_bfloat16* fr = f2 + (size_t)b*512;
#pragma unroll
    for (int n = 0; n < 8; n++) {
        const float* wr = w3 + n*512;
        float p = 0.f;
        for (int k = ln; k < 512; k += 32) p += __bfloat162float(fr[k])*wr[k];
#pragma unroll
        for (int o = 16; o; o >>= 1) p += __shfl_xor_sync(0xffffffffu, p, o);
        if (ln == 0) {
            float d = p + b3[n] - u[b*8+n];
            lsum += d*d;
        }
    }
    if (ln == 0) sp[w] = lsum;
    __syncthreads();
    if (threadIdx.x == 0) {
        float s = 0.f;
        for (int i = 0; i < 8; i++) s += sp[i];
        part[blockIdx.x] = s;
    }
}

__global__ void k_reduce(const float* __restrict__ part, float* __restrict__ out)
{
    __shared__ float sp[1024];
    int i = threadIdx.x;
    sp[i] = part[i];
    __syncthreads();
    for (int s = 512; s; s >>= 1) { if (i < s) sp[i] += sp[i+s]; __syncthreads(); }
    if (i == 0) out[0] = sp[0] * (1.f / (float)(B_*SD_));
}

// ============================ launch ============================
extern "C" void kernel_launch(void* const* d_in, const int* in_sizes, int n_in,
                              void* d_out, int out_size)
{
    const float* strokes  = (const float*)d_in[0];
    const float* canvas   = (const float*)d_in[1];
    const float* a_tar    = (const float*)d_in[2];
    const float* a_src    = (const float*)d_in[3];
    const float* t_in     = (const float*)d_in[4];
    const float* ce_w1    = (const float*)d_in[5];
    const float* ce_b1    = (const float*)d_in[6];
    const float* ce_w2    = (const float*)d_in[7];
    const float* ce_b2    = (const float*)d_in[8];
    const float* sp_w     = (const float*)d_in[9];
    const float* sp_b     = (const float*)d_in[10];
    const float* pos_emb  = (const float*)d_in[11];
    const float* adaln1_w = (const float*)d_in[12];
    const float* adaln1_b = (const float*)d_in[13];
    const float* inproj_w = (const float*)d_in[14];
    const float* inproj_b = (const float*)d_in[15];
    const float* outproj_w= (const float*)d_in[16];
    const float* outproj_b= (const float*)d_in[17];
    const float* adaln2_w = (const float*)d_in[18];
    const float* adaln2_b = (const float*)d_in[19];
    const float* ff1_w    = (const float*)d_in[20];
    const float* ff1_b    = (const float*)d_in[21];
    const float* ff2_w    = (const float*)d_in[22];
    const float* ff2_b    = (const float*)d_in[23];
    const float* on_g     = (const float*)d_in[24];
    const float* on_b     = (const float*)d_in[25];
    const float* fm_w1    = (const float*)d_in[26];
    const float* fm_b1    = (const float*)d_in[27];
    const float* fm_w2    = (const float*)d_in[28];
    const float* fm_b2    = (const float*)d_in[29];
    const float* fm_w3    = (const float*)d_in[30];
    const float* fm_b3    = (const float*)d_in[31];
    float* out = (float*)d_out;

    float *ss, *adb, *u, *part;
    __nv_bfloat16 *xb, *x2b, *hb, *cb, *canvb, *f1b, *f2b, *xinb;
    __nv_bfloat16 *wce1, *wce2, *wad, *winp, *wout, *wff1, *wff2, *wfm1, *wfm2;
    cudaGetSymbolAddress((void**)&ss,   g_ss);
    cudaGetSymbolAddress((void**)&adb,  g_adb);
    cudaGetSymbolAddress((void**)&u,    g_u);
    cudaGetSymbolAddress((void**)&part, g_part);
    cudaGetSymbolAddress((void**)&xb,   g_xb);
    cudaGetSymbolAddress((void**)&x2b,  g_x2b);
    cudaGetSymbolAddress((void**)&hb,   g_hb);
    cudaGetSymbolAddress((void**)&cb,   g_cb);
    cudaGetSymbolAddress((void**)&canvb,g_canvb);
    cudaGetSymbolAddress((void**)&f1b,  g_f1b);
    cudaGetSymbolAddress((void**)&f2b,  g_f2b);
    cudaGetSymbolAddress((void**)&xinb, g_xinb);
    cudaGetSymbolAddress((void**)&wce1, g_wce1);
    cudaGetSymbolAddress((void**)&wce2, g_wce2);
    cudaGetSymbolAddress((void**)&wad,  g_wad);
    cudaGetSymbolAddress((void**)&winp, g_winp);
    cudaGetSymbolAddress((void**)&wout, g_wout);
    cudaGetSymbolAddress((void**)&wff1, g_wff1);
    cudaGetSymbolAddress((void**)&wff2, g_wff2);
    cudaGetSymbolAddress((void**)&wfm1, g_wfm1);
    cudaGetSymbolAddress((void**)&wfm2, g_wfm2);

    cudaFuncSetAttribute(gemm_tc<0,0>, cudaFuncAttributeMaxDynamicSharedMemorySize, GSMEM);
    cudaFuncSetAttribute(gemm_tc<0,1>, cudaFuncAttributeMaxDynamicSharedMemorySize, GSMEM);
    cudaFuncSetAttribute(gemm_tc<1,1>, cudaFuncAttributeMaxDynamicSharedMemorySize, GSMEM);
    cudaFuncSetAttribute(gemm_tc<2,1>, cudaFuncAttributeMaxDynamicSharedMemorySize, GSMEM);
    cudaFuncSetAttribute(k_attn,       cudaFuncAttributeMaxDynamicSharedMemorySize, ASMEM);

    // weight + input bf16 conversion (R10 order)
    k_cvt<<<1024, 256>>>(canvas,   canvb, B_*384);
    k_cvt<<<256,  256>>>(ce_w1,    wce1,  512*384);
    k_cvt<<<256,  256>>>(ce_w2,    wce2,  256*512);
    k_cvt<<<512,  256>>>(adaln1_w, wad,             L_*512*256);
    k_cvt<<<512,  256>>>(adaln2_w, wad + 3072*256,  L_*512*256);
    k_cat<<<24, 256>>>(adaln1_b, adaln2_b, adb);
    k_cvt<<<512,  256>>>(inproj_w, winp,  L_*768*256);
    k_cvt<<<512,  256>>>(outproj_w,wout,  L_*256*256);
    k_cvt<<<1024, 256>>>(ff1_w,    wff1,  L_*1024*256);
    k_cvt<<<1024, 256>>>(ff2_w,    wff2,  L_*256*1024);
    k_cvt<<<256,  256>>>(fm_w2,    wfm2,  512*512);
    k_padw<<<512, KP_>>>(fm_w1, wfm1);

    // canvas encoder
    gemm_tc<1,1><<<dim3(4,  64), 256, GSMEM>>>(canvb, wce1, ce_b1, f1b, nullptr, B_, 512, 384);
    gemm_tc<0,1><<<dim3(2,  64), 256, GSMEM>>>(f1b,   wce2, ce_b2, cb,  nullptr, B_, 256, 512);

    // all 12 adaLN projections in one batched GEMM: ss[B, 6144]
    gemm_tc<0,0><<<dim3(48, 64), 256, GSMEM>>>(cb, wad, adb, ss, nullptr, B_, NAD_, 256);

    // stroke projection
    k_stroke<<<BT_, 256>>>(strokes, sp_w, sp_b, pos_emb, xb);

    for (int l = 0; l < L_; l++) {
        k_modln<<<BT_/8, 256>>>(xb, ss, x2b, l*512);
        gemm_tc<0,1><<<dim3(6, 1920), 256, GSMEM>>>(x2b, winp + (size_t)l*768*256,
                                                    inproj_b + l*768, hb, nullptr, BT_, 768, 256);
        k_attn<<<B_, 256, ASMEM>>>(hb, x2b);
        gemm_tc<2,1><<<dim3(2, 1920), 256, GSMEM>>>(x2b, wout + (size_t)l*256*256,
                                                    outproj_b + l*256, xb, xb, BT_, 256, 256);
        k_modln<<<BT_/8, 256>>>(xb, ss, x2b, 3072 + l*512);
        gemm_tc<1,1><<<dim3(8, 1920), 256, GSMEM>>>(x2b, wff1 + (size_t)l*1024*256,
                                                    ff1_b + l*1024, hb, nullptr, BT_, 1024, 256);
        gemm_tc<2,1><<<dim3(2, 1920), 256, GSMEM>>>(hb, wff2 + (size_t)l*256*1024,
                                                    ff2_b + l*256, xb, xb, BT_, 256, 1024);
    }

    // output head
    k_head<<<B_/8, 256>>>(xb, on_g, on_b, a_tar, a_src, t_in, xinb, u);
    gemm_tc<1,1><<<dim3(4, 64), 256, GSMEM>>>(xinb, wfm1, fm_b1, f1b, nullptr, B_, 512, KP_);
    gemm_tc<1,1><<<dim3(4, 64), 256, GSMEM>>>(f1b,  wfm2, fm_b2, f2b, nullptr, B_, 512, 512);
    k_fm3<<<B_/8, 256>>>(f2b, fm_w3, fm_b3, u, part);
    k_reduce<<<1, 1024>>>(part, out);
}